// round 11
// baseline (speedup 1.0000x reference)
#include <cuda_runtime.h>
#include <cuda_bf16.h>
#include <cstdint>

// Problem shapes (fixed by the dataset)
#define B_ 16
#define N_ 512
#define C_ 384
#define K_ 64
#define NN_ (N_*N_)

// Scratch (no allocs allowed -> __device__ globals)
__device__ float g_qpart[B_][8][C_];
__device__ float g_attn[B_*K_];
__device__ __nv_bfloat16 g_tmh[(size_t)B_*NN_];   // tm hi  [B][512][512]
__device__ __nv_bfloat16 g_tml[(size_t)B_*NN_];   // tm lo
__device__ __nv_bfloat16 g_xTh[(size_t)B_*C_*N_]; // xT hi  [B][C][N]
__device__ __nv_bfloat16 g_xTl[(size_t)B_*C_*N_];
__device__ __nv_bfloat16 g_yh[(size_t)B_*N_*C_];  // y hi   [B*N][C]
__device__ __nv_bfloat16 g_yl[(size_t)B_*N_*C_];
__device__ __nv_bfloat16 g_Wh[C_*C_];             // W hi   [C][C]
__device__ __nv_bfloat16 g_Wl[C_*C_];

__device__ __forceinline__ uint32_t smem_u32(const void* p) {
    uint32_t a;
    asm("{ .reg .u64 t; cvta.to.shared.u64 t, %1; cvt.u32.u64 %0, t; }"
        : "=r"(a) : "l"(p));
    return a;
}
__device__ __forceinline__ void cp_async16(uint32_t dst, const void* src) {
    asm volatile("cp.async.cg.shared.global [%0], [%1], 16;"
                 :: "r"(dst), "l"(src) : "memory");
}
__device__ __forceinline__ void cp_commit() {
    asm volatile("cp.async.commit_group;" ::: "memory");
}
template <int NMax>
__device__ __forceinline__ void cp_wait() {
    asm volatile("cp.async.wait_group %0;" :: "n"(NMax) : "memory");
}
__device__ __forceinline__ void ldsm_x4(uint32_t* r, uint32_t addr) {
    asm volatile("ldmatrix.sync.aligned.m8n8.x4.shared.b16 {%0,%1,%2,%3}, [%4];"
        : "=r"(r[0]), "=r"(r[1]), "=r"(r[2]), "=r"(r[3]) : "r"(addr));
}
__device__ __forceinline__ void mma_bf16(float* c, const uint32_t* a, const uint32_t* b) {
    asm volatile(
        "mma.sync.aligned.m16n8k16.row.col.f32.bf16.bf16.f32 "
        "{%0,%1,%2,%3}, {%4,%5,%6,%7}, {%8,%9}, {%0,%1,%2,%3};"
        : "+f"(c[0]), "+f"(c[1]), "+f"(c[2]), "+f"(c[3])
        : "r"(a[0]), "r"(a[1]), "r"(a[2]), "r"(a[3]), "r"(b[0]), "r"(b[1]));
}
__device__ __forceinline__ void fma2(unsigned long long& d, unsigned long long a,
                                     unsigned long long b) {
    asm("fma.rn.f32x2 %0, %1, %2, %0;" : "+l"(d) : "l"(a), "l"(b));
}
__device__ __forceinline__ uint32_t pack_bf16(__nv_bfloat16 a, __nv_bfloat16 b) {
    return (uint32_t)__bfloat16_as_ushort(a) | ((uint32_t)__bfloat16_as_ushort(b) << 16);
}
__device__ __forceinline__ void split_bf16(float v, __nv_bfloat16& h, __nv_bfloat16& l) {
    h = __float2bfloat16_rn(v);
    l = __float2bfloat16_rn(v - __bfloat162float(h));
}

// ---------------------------------------------------------------------------
// Kernel 1 (launch #1): fused pool partials + transpose_x(+split) + W split.
// grid (16, 12, 18): z<16 transpose slices; z==16 W; z==17 pooling.
// ---------------------------------------------------------------------------
__global__ void convert_kernel(const float* __restrict__ x,
                               const float* __restrict__ W) {
    if (blockIdx.z == 16) {
        int tid = (blockIdx.y * 16 + blockIdx.x) * 256 +
                  threadIdx.y * 32 + threadIdx.x;     // 192 blocks * 256
        for (int i = tid; i < C_ * C_; i += 192 * 256) {
            __nv_bfloat16 h, l;
            split_bf16(W[i], h, l);
            g_Wh[i] = h;
            g_Wl[i] = l;
        }
        return;
    }
    if (blockIdx.z == 17) {
        // pooling partials: 192 blocks of 256 -> use first 128 blocks (B*8)
        int blk = blockIdx.y * 16 + blockIdx.x;       // 0..191
        if (blk >= B_ * 8) return;
        int b = blk >> 3, seg = blk & 7;
        int t = threadIdx.y * 32 + threadIdx.x;       // 0..255
        const float* xb = x + (size_t)b * N_ * C_ + (size_t)seg * 64 * C_;
        // 256 threads cover 384 channels: thread t does c=t and maybe c=t+256
        for (int c = t; c < C_; c += 256) {
            float s = 0.f;
            #pragma unroll 8
            for (int n = 0; n < 64; n++) s += xb[(size_t)n * C_ + c];
            g_qpart[b][seg][c] = s;
        }
        return;
    }
    __shared__ float t[32][33];
    int b = blockIdx.z;
    int n0 = blockIdx.x * 32, c0 = blockIdx.y * 32;
    int tx = threadIdx.x, ty = threadIdx.y;   // 32 x 8
    #pragma unroll
    for (int i = 0; i < 4; i++)
        t[ty + i * 8][tx] = x[(size_t)b * N_ * C_ + (size_t)(n0 + ty + i * 8) * C_ + c0 + tx];
    __syncthreads();
    #pragma unroll
    for (int i = 0; i < 4; i++) {
        float v = t[tx][ty + i * 8];
        __nv_bfloat16 h, l;
        split_bf16(v, h, l);
        size_t o = (size_t)b * C_ * N_ + (size_t)(c0 + ty + i * 8) * N_ + n0 + tx;
        g_xTh[o] = h;
        g_xTl[o] = l;
    }
}

// ---------------------------------------------------------------------------
// Kernel 2 (launch #2): finish pool + normalize + logits + softmax -> g_attn
// ---------------------------------------------------------------------------
__global__ void attn_kernel(const float* __restrict__ centers) {
    int b = blockIdx.x;
    int tid = threadIdx.x;
    __shared__ float s_q[C_];
    __shared__ float s_red[C_];
    __shared__ float s_logit[K_];
    __shared__ float s_mx, s_den;

    float sum = 0.f;
    #pragma unroll
    for (int seg = 0; seg < 8; seg++) sum += g_qpart[b][seg][tid];
    s_q[tid] = sum * (1.0f / N_);
    __syncthreads();

    float v = s_q[tid];
    s_red[tid] = v * v;
    __syncthreads();
    if (tid < 128) s_red[tid] += s_red[tid + 128] + s_red[tid + 256];
    __syncthreads();
    for (int s = 64; s > 0; s >>= 1) {
        if (tid < s) s_red[tid] += s_red[tid + s];
        __syncthreads();
    }
    float qnorm = sqrtf(s_red[0]);

    if (tid < K_) {
        float dot = 0.f, cs = 0.f;
        #pragma unroll 4
        for (int c = 0; c < C_; c++) {
            float w = centers[(size_t)c * K_ + tid];
            dot += s_q[c] * w;
            cs  += w * w;
        }
        float denom = fmaxf(qnorm, 1e-12f) * fmaxf(sqrtf(cs), 1e-12f);
        s_logit[tid] = dot / denom;
    }
    __syncthreads();

    if (tid == 0) {
        float mx = -1e30f;
        for (int k = 0; k < K_; k++) mx = fmaxf(mx, s_logit[k]);
        float den = 0.f;
        for (int k = 0; k < K_; k++) den += expf(s_logit[k] - mx);
        s_mx = mx; s_den = den;
    }
    __syncthreads();
    if (tid < K_) g_attn[b * K_ + tid] = expf(s_logit[tid] - s_mx) / s_den;
}

// ---------------------------------------------------------------------------
// Kernel 3 (launch #3): tm[b,:] = sum_k attn[b,k]*tran[k,:]; bf16 hi/lo out.
// FFMA2 with LEAN registers: float2/thread, 16 u64 accumulators (32 regs),
// splatted {w,w} weights in smem.
// ---------------------------------------------------------------------------
__global__ __launch_bounds__(128)
void tm_kernel(const float* __restrict__ tran) {
    __shared__ unsigned long long s_w[K_][B_];    // splatted {w,w}, 8KB
    int tid = threadIdx.x;
    for (int i = tid; i < K_ * B_; i += 128) {
        int k = i >> 4, b = i & 15;
        float w = g_attn[b * K_ + k];
        unsigned long long ww =
            (unsigned long long)__float_as_uint(w) |
            ((unsigned long long)__float_as_uint(w) << 32);
        s_w[k][b] = ww;
    }
    __syncthreads();

    const size_t idx2 = (size_t)blockIdx.x * 128 + tid;    // float2 index
    const unsigned long long* t2 = (const unsigned long long*)tran;

    unsigned long long acc[B_];
    #pragma unroll
    for (int b = 0; b < B_; b++) acc[b] = 0ull;

    #pragma unroll 4
    for (int k = 0; k < K_; k++) {
        unsigned long long v = t2[(size_t)k * (NN_/2) + idx2];
        #pragma unroll
        for (int b = 0; b < B_; b++)
            fma2(acc[b], s_w[k][b], v);
    }

    uint32_t* th = (uint32_t*)g_tmh;
    uint32_t* tl = (uint32_t*)g_tml;
    #pragma unroll
    for (int b = 0; b < B_; b++) {
        float vx = __uint_as_float((uint32_t)acc[b]);
        float vy = __uint_as_float((uint32_t)(acc[b] >> 32));
        __nv_bfloat16 hx, lx, hy, ly;
        split_bf16(vx, hx, lx);
        split_bf16(vy, hy, ly);
        size_t o = (size_t)b * (NN_/2) + idx2;
        th[o] = pack_bf16(hx, hy);
        tl[o] = pack_bf16(lx, ly);
    }
}

// ---------------------------------------------------------------------------
// bf16x3 tensor-core GEMM, hi/lo pre-split operands. (unchanged from R10)
// CTA 128x64x32, 8 warps (4m x 2n), warp tile 32x32.
// ---------------------------------------------------------------------------
#define TBM 128
#define TBN 64
#define TBK 32
#define AH_BYTES (TBM*TBK*2)           // 8192
#define BH_BYTES (TBN*TBK*2)           // 4096
#define STAGE_BYTES (2*AH_BYTES + 2*BH_BYTES)  // 24576
#define NSTAGE 3
#define GSMEM_BYTES (NSTAGE*STAGE_BYTES)       // 73728

template <int EPI>
__global__ __launch_bounds__(256, 3)
void gemm_bf16(const __nv_bfloat16* __restrict__ Ah, const __nv_bfloat16* __restrict__ Al,
               const __nv_bfloat16* __restrict__ Bh, const __nv_bfloat16* __restrict__ Bl,
               float* __restrict__ Cf, __nv_bfloat16* __restrict__ Ch,
               __nv_bfloat16* __restrict__ Cl, const float* __restrict__ bias,
               int Kk, int lda, int ldb, int ldc,
               size_t sA, size_t sB, size_t sC) {
    extern __shared__ char sm[];

    const int tid = threadIdx.x;
    const int warp = tid >> 5, lane = tid & 31;
    const int wm = warp >> 1, wn = warp & 1;      // 4 x 2 warp grid
    const int g = lane >> 2, t4 = lane & 3;

    const int m0 = blockIdx.x * TBM, n0 = blockIdx.y * TBN;
    const __nv_bfloat16* Ahb = Ah + (size_t)blockIdx.z * sA;
    const __nv_bfloat16* Alb = Al + (size_t)blockIdx.z * sA;
    const __nv_bfloat16* Bhb = Bh + (size_t)blockIdx.z * sB;
    const __nv_bfloat16* Blb = Bl + (size_t)blockIdx.z * sB;

    const uint32_t smb = smem_u32(sm);

    auto issue_copy = [&](int s, int k0) {
        uint32_t st = smb + (uint32_t)s * STAGE_BYTES;
        #pragma unroll
        for (int i = 0; i < 4; i++) {
            int id = tid + 256 * i;
            int hi = (id < 512);
            int cid = hi ? id : id - 512;
            int r = cid >> 2, c = cid & 3;
            uint32_t d = st + (hi ? 0u : (uint32_t)AH_BYTES)
                       + (uint32_t)(r * 64 + ((c ^ ((r >> 1) & 3)) << 4));
            const __nv_bfloat16* src = (hi ? Ahb : Alb)
                                     + (size_t)(m0 + r) * lda + k0 + c * 8;
            cp_async16(d, src);
        }
        uint32_t bst = st + 2 * AH_BYTES;
        #pragma unroll
        for (int i = 0; i < 2; i++) {
            int hi = (i == 0);
            int r = tid >> 2, c = tid & 3;
            uint32_t d = bst + (hi ? 0u : (uint32_t)BH_BYTES)
                       + (uint32_t)(r * 64 + ((c ^ ((r >> 1) & 3)) << 4));
            const __nv_bfloat16* src = (hi ? Bhb : Blb)
                                     + (size_t)(n0 + r) * ldb + k0 + c * 8;
            cp_async16(d, src);
        }
    };

    float acc[2][4][4];
    #pragma unroll
    for (int mt = 0; mt < 2; mt++)
        #pragma unroll
        for (int nt = 0; nt < 4; nt++)
            #pragma unroll
            for (int q = 0; q < 4; q++) acc[mt][nt][q] = 0.f;

    const int lrA = lane & 15, lkA = (lane >> 4) & 1;
    int offA[2], qA[2];
    #pragma unroll
    for (int mt = 0; mt < 2; mt++) {
        int r = wm * 32 + mt * 16 + lrA;
        offA[mt] = r * 64;
        qA[mt] = (r >> 1) & 3;
    }
    const int b_ntloc = (lane >> 4) & 1, b_kh = (lane >> 3) & 1;
    int offB[2], qB[2];
    #pragma unroll
    for (int P = 0; P < 2; P++) {
        int r = wn * 32 + P * 16 + b_ntloc * 8 + (lane & 7);
        offB[P] = r * 64;
        qB[P] = (r >> 1) & 3;
    }

    auto compute = [&](int s) {
        uint32_t st = smb + (uint32_t)s * STAGE_BYTES;
        uint32_t bst = st + 2 * AH_BYTES;
        #pragma unroll
        for (int ks = 0; ks < 2; ks++) {
            uint32_t ah[2][4], al[2][4], bh[2][4], bl[2][4];
            #pragma unroll
            for (int mt = 0; mt < 2; mt++) {
                uint32_t ad = st + offA[mt] + ((((ks * 2 + lkA) ^ qA[mt])) << 4);
                ldsm_x4(ah[mt], ad);
                ldsm_x4(al[mt], ad + AH_BYTES);
            }
            #pragma unroll
            for (int P = 0; P < 2; P++) {
                uint32_t bd = bst + offB[P] + ((((ks * 2 + b_kh) ^ qB[P])) << 4);
                ldsm_x4(bh[P], bd);
                ldsm_x4(bl[P], bd + BH_BYTES);
            }
            #pragma unroll
            for (int mt = 0; mt < 2; mt++)
                #pragma unroll
                for (int nt = 0; nt < 4; nt++)
                    mma_bf16(acc[mt][nt], ah[mt], &bh[nt >> 1][(nt & 1) * 2]);
            #pragma unroll
            for (int mt = 0; mt < 2; mt++)
                #pragma unroll
                for (int nt = 0; nt < 4; nt++)
                    mma_bf16(acc[mt][nt], ah[mt], &bl[nt >> 1][(nt & 1) * 2]);
            #pragma unroll
            for (int mt = 0; mt < 2; mt++)
                #pragma unroll
                for (int nt = 0; nt < 4; nt++)
                    mma_bf16(acc[mt][nt], al[mt], &bh[nt >> 1][(nt & 1) * 2]);
        }
    };

    const int nch = Kk / TBK;

    #pragma unroll
    for (int p = 0; p < NSTAGE - 1; p++) {
        if (p < nch) issue_copy(p, p * TBK);
        cp_commit();
    }

    for (int ch = 0; ch < nch; ch++) {
        cp_wait<NSTAGE - 2>();
        __syncthreads();
        int nxt = ch + NSTAGE - 1;
        if (nxt < nch) issue_copy(nxt % NSTAGE, nxt * TBK);
        cp_commit();
        compute(ch % NSTAGE);
    }

    #pragma unroll
    for (int mt = 0; mt < 2; mt++) {
        int r0 = m0 + wm * 32 + mt * 16 + g;
        #pragma unroll
        for (int nt = 0; nt < 4; nt++) {
            int col = n0 + wn * 32 + nt * 8 + t4 * 2;
            if (EPI == 0) {
                __nv_bfloat16 h0, l0, h1, l1;
                uint32_t* chp = (uint32_t*)Ch;
                uint32_t* clp = (uint32_t*)Cl;
                size_t base = (size_t)blockIdx.z * sC;
                split_bf16(acc[mt][nt][0], h0, l0);
                split_bf16(acc[mt][nt][1], h1, l1);
                size_t o0 = (base + (size_t)r0 * ldc + col) >> 1;
                chp[o0] = pack_bf16(h0, h1);
                clp[o0] = pack_bf16(l0, l1);
                split_bf16(acc[mt][nt][2], h0, l0);
                split_bf16(acc[mt][nt][3], h1, l1);
                size_t o1 = (base + (size_t)(r0 + 8) * ldc + col) >> 1;
                chp[o1] = pack_bf16(h0, h1);
                clp[o1] = pack_bf16(l0, l1);
            } else {
                float b0 = __ldg(bias + col), b1 = __ldg(bias + col + 1);
                float* p0 = Cf + (size_t)r0 * ldc + col;
                float* p1 = Cf + (size_t)(r0 + 8) * ldc + col;
                *(float2*)p0 = make_float2(acc[mt][nt][0] + b0, acc[mt][nt][1] + b1);
                *(float2*)p1 = make_float2(acc[mt][nt][2] + b0, acc[mt][nt][3] + b1);
            }
        }
    }
}

// ---------------------------------------------------------------------------
extern "C" void kernel_launch(void* const* d_in, const int* in_sizes, int n_in,
                              void* d_out, int out_size) {
    const float* x       = (const float*)d_in[0];  // [B,N,C]
    const float* centers = (const float*)d_in[1];  // [C,K]
    const float* tran_ms = (const float*)d_in[2];  // [K,N,N]
    const float* proj_w  = (const float*)d_in[3];  // [C,C]
    const float* proj_b  = (const float*)d_in[4];  // [C]
    float* out = (float*)d_out;                    // [B,N,C]

    __nv_bfloat16 *tmh, *tml, *xth, *xtl, *yh, *yl, *wh, *wl;
    cudaGetSymbolAddress((void**)&tmh, g_tmh);
    cudaGetSymbolAddress((void**)&tml, g_tml);
    cudaGetSymbolAddress((void**)&xth, g_xTh);
    cudaGetSymbolAddress((void**)&xtl, g_xTl);
    cudaGetSymbolAddress((void**)&yh, g_yh);
    cudaGetSymbolAddress((void**)&yl, g_yl);
    cudaGetSymbolAddress((void**)&wh, g_Wh);
    cudaGetSymbolAddress((void**)&wl, g_Wl);

    cudaFuncSetAttribute(gemm_bf16<0>, cudaFuncAttributeMaxDynamicSharedMemorySize,
                         GSMEM_BYTES);
    cudaFuncSetAttribute(gemm_bf16<1>, cudaFuncAttributeMaxDynamicSharedMemorySize,
                         GSMEM_BYTES);

    // launch #1: conversions + pooling partials (fused)
    convert_kernel<<<dim3(N_/32, C_/32, B_ + 2), dim3(32, 8)>>>(x, proj_w);

    // launch #2: routing weights
    attn_kernel<<<B_, C_>>>(centers);

    // launch #3: tm = attn @ tran_ms -> bf16 hi/lo (FFMA2, lean regs)
    tm_kernel<<<(NN_/2) / 128, 128>>>(tran_ms);

    // launch #4 (ncu capture slot): y[b] = tm[b] @ x[b]
    gemm_bf16<0><<<dim3(N_/TBM, C_/TBN, B_), 256, GSMEM_BYTES>>>(
        tmh, tml, xth, xtl, nullptr, yh, yl, nullptr,
        /*K=*/N_, /*lda=*/N_, /*ldb=*/N_, /*ldc=*/C_,
        (size_t)NN_, (size_t)C_ * N_, (size_t)N_ * C_);

    // launch #5: out = y @ W^T + b
    gemm_bf16<1><<<dim3((B_*N_)/TBM, C_/TBN, 1), 256, GSMEM_BYTES>>>(
        yh, yl, wh, wl, out, nullptr, nullptr, proj_b,
        /*K=*/C_, /*lda=*/C_, /*ldb=*/C_, /*ldc=*/C_,
        0, 0, 0);
}

// round 12
// speedup vs baseline: 1.3984x; 1.3984x over previous
#include <cuda_runtime.h>
#include <cuda_fp16.h>
#include <cstdint>

// Problem shapes (fixed by the dataset)
#define B_ 16
#define N_ 512
#define C_ 384
#define K_ 64
#define NN_ (N_*N_)

// Scratch (no allocs allowed -> __device__ globals)
__device__ float g_qpart[B_][8][C_];
__device__ float g_attn[B_*K_];
__device__ __half g_tm16[(size_t)B_*NN_];    // tm   [B][512][512] fp16
__device__ __half g_xT16[(size_t)B_*C_*N_];  // xT   [B][C][N]    fp16
__device__ __half g_y16[(size_t)B_*N_*C_];   // y    [B*N][C]     fp16
__device__ __half g_W16[C_*C_];              // W    [C][C]       fp16

__device__ __forceinline__ uint32_t smem_u32(const void* p) {
    uint32_t a;
    asm("{ .reg .u64 t; cvta.to.shared.u64 t, %1; cvt.u32.u64 %0, t; }"
        : "=r"(a) : "l"(p));
    return a;
}
__device__ __forceinline__ void cp_async16(uint32_t dst, const void* src) {
    asm volatile("cp.async.cg.shared.global [%0], [%1], 16;"
                 :: "r"(dst), "l"(src) : "memory");
}
__device__ __forceinline__ void cp_commit() {
    asm volatile("cp.async.commit_group;" ::: "memory");
}
template <int NMax>
__device__ __forceinline__ void cp_wait() {
    asm volatile("cp.async.wait_group %0;" :: "n"(NMax) : "memory");
}
__device__ __forceinline__ void ldsm_x4(uint32_t* r, uint32_t addr) {
    asm volatile("ldmatrix.sync.aligned.m8n8.x4.shared.b16 {%0,%1,%2,%3}, [%4];"
        : "=r"(r[0]), "=r"(r[1]), "=r"(r[2]), "=r"(r[3]) : "r"(addr));
}
__device__ __forceinline__ void mma_fp16(float* c, const uint32_t* a, const uint32_t* b) {
    asm volatile(
        "mma.sync.aligned.m16n8k16.row.col.f32.f16.f16.f32 "
        "{%0,%1,%2,%3}, {%4,%5,%6,%7}, {%8,%9}, {%0,%1,%2,%3};"
        : "+f"(c[0]), "+f"(c[1]), "+f"(c[2]), "+f"(c[3])
        : "r"(a[0]), "r"(a[1]), "r"(a[2]), "r"(a[3]), "r"(b[0]), "r"(b[1]));
}
__device__ __forceinline__ uint32_t pack_h2(float a, float b) {
    __half2 h = __floats2half2_rn(a, b);
    return *(uint32_t*)&h;
}

// ---------------------------------------------------------------------------
// Kernel 1 (launch #1): fused pool partials + transpose_x(+fp16) + W fp16.
// grid (16, 12, 18): z<16 transpose slices; z==16 W; z==17 pooling.
// ---------------------------------------------------------------------------
__global__ void convert_kernel(const float* __restrict__ x,
                               const float* __restrict__ W) {
    if (blockIdx.z == 16) {
        int tid = (blockIdx.y * 16 + blockIdx.x) * 256 +
                  threadIdx.y * 32 + threadIdx.x;
        for (int i = tid; i < C_ * C_; i += 192 * 256)
            g_W16[i] = __float2half_rn(W[i]);
        return;
    }
    if (blockIdx.z == 17) {
        int blk = blockIdx.y * 16 + blockIdx.x;       // 0..191
        if (blk >= B_ * 8) return;
        int b = blk >> 3, seg = blk & 7;
        int t = threadIdx.y * 32 + threadIdx.x;       // 0..255
        const float* xb = x + (size_t)b * N_ * C_ + (size_t)seg * 64 * C_;
        for (int c = t; c < C_; c += 256) {
            float s = 0.f;
            #pragma unroll 8
            for (int n = 0; n < 64; n++) s += xb[(size_t)n * C_ + c];
            g_qpart[b][seg][c] = s;
        }
        return;
    }
    __shared__ float t[32][33];
    int b = blockIdx.z;
    int n0 = blockIdx.x * 32, c0 = blockIdx.y * 32;
    int tx = threadIdx.x, ty = threadIdx.y;   // 32 x 8
    #pragma unroll
    for (int i = 0; i < 4; i++)
        t[ty + i * 8][tx] = x[(size_t)b * N_ * C_ + (size_t)(n0 + ty + i * 8) * C_ + c0 + tx];
    __syncthreads();
    #pragma unroll
    for (int i = 0; i < 4; i++) {
        float v = t[tx][ty + i * 8];
        size_t o = (size_t)b * C_ * N_ + (size_t)(c0 + ty + i * 8) * N_ + n0 + tx;
        g_xT16[o] = __float2half_rn(v);
    }
}

// ---------------------------------------------------------------------------
// Kernel 2 (launch #2): finish pool + normalize + logits + softmax -> g_attn
// ---------------------------------------------------------------------------
__global__ void attn_kernel(const float* __restrict__ centers) {
    int b = blockIdx.x;
    int tid = threadIdx.x;
    __shared__ float s_q[C_];
    __shared__ float s_red[C_];
    __shared__ float s_logit[K_];
    __shared__ float s_mx, s_den;

    float sum = 0.f;
    #pragma unroll
    for (int seg = 0; seg < 8; seg++) sum += g_qpart[b][seg][tid];
    s_q[tid] = sum * (1.0f / N_);
    __syncthreads();

    float v = s_q[tid];
    s_red[tid] = v * v;
    __syncthreads();
    if (tid < 128) s_red[tid] += s_red[tid + 128] + s_red[tid + 256];
    __syncthreads();
    for (int s = 64; s > 0; s >>= 1) {
        if (tid < s) s_red[tid] += s_red[tid + s];
        __syncthreads();
    }
    float qnorm = sqrtf(s_red[0]);

    if (tid < K_) {
        float dot = 0.f, cs = 0.f;
        #pragma unroll 4
        for (int c = 0; c < C_; c++) {
            float w = centers[(size_t)c * K_ + tid];
            dot += s_q[c] * w;
            cs  += w * w;
        }
        float denom = fmaxf(qnorm, 1e-12f) * fmaxf(sqrtf(cs), 1e-12f);
        s_logit[tid] = dot / denom;
    }
    __syncthreads();

    if (tid == 0) {
        float mx = -1e30f;
        for (int k = 0; k < K_; k++) mx = fmaxf(mx, s_logit[k]);
        float den = 0.f;
        for (int k = 0; k < K_; k++) den += expf(s_logit[k] - mx);
        s_mx = mx; s_den = den;
    }
    __syncthreads();
    if (tid < K_) g_attn[b * K_ + tid] = expf(s_logit[tid] - s_mx) / s_den;
}

// ---------------------------------------------------------------------------
// Kernel 3 (launch #3): tm[b,:] = sum_k attn[b,k]*tran[k,:] -> fp16.
// R7-proven form: float2/thread, scalar FFMA, attn [k][16] in smem.
// ---------------------------------------------------------------------------
__global__ __launch_bounds__(128)
void tm_kernel(const float* __restrict__ tran) {
    __shared__ float s_attn[K_][B_];
    int tid = threadIdx.x;
    for (int i = tid; i < K_ * B_; i += 128) {
        int k = i >> 4, b = i & 15;
        s_attn[k][b] = g_attn[b * K_ + k];
    }
    __syncthreads();

    const size_t idx2 = (size_t)blockIdx.x * 128 + tid;    // float2 index
    const float2* t2 = (const float2*)tran;

    float2 acc[B_];
    #pragma unroll
    for (int b = 0; b < B_; b++) acc[b] = make_float2(0.f, 0.f);

    #pragma unroll 4
    for (int k = 0; k < K_; k++) {
        float2 v = t2[(size_t)k * (NN_/2) + idx2];
        const float4* w4 = (const float4*)&s_attn[k][0];
        #pragma unroll
        for (int j = 0; j < 4; j++) {
            float4 w = w4[j];
            acc[4*j+0].x = fmaf(w.x, v.x, acc[4*j+0].x);
            acc[4*j+0].y = fmaf(w.x, v.y, acc[4*j+0].y);
            acc[4*j+1].x = fmaf(w.y, v.x, acc[4*j+1].x);
            acc[4*j+1].y = fmaf(w.y, v.y, acc[4*j+1].y);
            acc[4*j+2].x = fmaf(w.z, v.x, acc[4*j+2].x);
            acc[4*j+2].y = fmaf(w.z, v.y, acc[4*j+2].y);
            acc[4*j+3].x = fmaf(w.w, v.x, acc[4*j+3].x);
            acc[4*j+3].y = fmaf(w.w, v.y, acc[4*j+3].y);
        }
    }

    uint32_t* th = (uint32_t*)g_tm16;
    #pragma unroll
    for (int b = 0; b < B_; b++)
        th[(size_t)b * (NN_/2) + idx2] = pack_h2(acc[b].x, acc[b].y);
}

// ---------------------------------------------------------------------------
// fp16 tensor-core GEMM (mma.sync m16n8k16 f32.f16.f16.f32), single term.
// CTA 128x64x32, 8 warps (4m x 2n), warp tile 32x32.
// cp.async 3-stage pipeline (12KB/stage), one __syncthreads per chunk.
// EPI=0: write fp16 (gemm1 -> y16). EPI=1: write f32 + bias (final out).
// ---------------------------------------------------------------------------
#define TBM 128
#define TBN 64
#define TBK 32
#define A_BYTES (TBM*TBK*2)            // 8192
#define B_BYTES (TBN*TBK*2)            // 4096
#define STAGE_BYTES (A_BYTES + B_BYTES)        // 12288
#define NSTAGE 3
#define GSMEM_BYTES (NSTAGE*STAGE_BYTES)       // 36864

template <int EPI>
__global__ __launch_bounds__(256, 3)
void gemm_fp16(const __half* __restrict__ A, const __half* __restrict__ Bm,
               float* __restrict__ Cf, __half* __restrict__ Ch,
               const float* __restrict__ bias,
               int Kk, int lda, int ldb, int ldc,
               size_t sA, size_t sB, size_t sC) {
    extern __shared__ char sm[];

    const int tid = threadIdx.x;
    const int warp = tid >> 5, lane = tid & 31;
    const int wm = warp >> 1, wn = warp & 1;      // 4 x 2 warp grid
    const int g = lane >> 2, t4 = lane & 3;

    const int m0 = blockIdx.x * TBM, n0 = blockIdx.y * TBN;
    const __half* Ab = A  + (size_t)blockIdx.z * sA;
    const __half* Bb = Bm + (size_t)blockIdx.z * sB;

    const uint32_t smb = smem_u32(sm);

    // A: 512 16B chunks -> 2/thread. B: 256 -> 1/thread.
    auto issue_copy = [&](int s, int k0) {
        uint32_t st = smb + (uint32_t)s * STAGE_BYTES;
        #pragma unroll
        for (int i = 0; i < 2; i++) {
            int id = tid + 256 * i;
            int r = id >> 2, c = id & 3;
            uint32_t d = st + (uint32_t)(r * 64 + ((c ^ ((r >> 1) & 3)) << 4));
            cp_async16(d, Ab + (size_t)(m0 + r) * lda + k0 + c * 8);
        }
        {
            uint32_t bst = st + A_BYTES;
            int r = tid >> 2, c = tid & 3;
            uint32_t d = bst + (uint32_t)(r * 64 + ((c ^ ((r >> 1) & 3)) << 4));
            cp_async16(d, Bb + (size_t)(n0 + r) * ldb + k0 + c * 8);
        }
    };

    float acc[2][4][4];
    #pragma unroll
    for (int mt = 0; mt < 2; mt++)
        #pragma unroll
        for (int nt = 0; nt < 4; nt++)
            #pragma unroll
            for (int q = 0; q < 4; q++) acc[mt][nt][q] = 0.f;

    const int lrA = lane & 15, lkA = (lane >> 4) & 1;
    int offA[2], qA[2];
    #pragma unroll
    for (int mt = 0; mt < 2; mt++) {
        int r = wm * 32 + mt * 16 + lrA;
        offA[mt] = r * 64;
        qA[mt] = (r >> 1) & 3;
    }
    const int b_ntloc = (lane >> 4) & 1, b_kh = (lane >> 3) & 1;
    int offB[2], qB[2];
    #pragma unroll
    for (int P = 0; P < 2; P++) {
        int r = wn * 32 + P * 16 + b_ntloc * 8 + (lane & 7);
        offB[P] = r * 64;
        qB[P] = (r >> 1) & 3;
    }

    auto compute = [&](int s) {
        uint32_t st = smb + (uint32_t)s * STAGE_BYTES;
        uint32_t bst = st + A_BYTES;
        #pragma unroll
        for (int ks = 0; ks < 2; ks++) {
            uint32_t ah[2][4], bh[2][4];
            #pragma unroll
            for (int mt = 0; mt < 2; mt++)
                ldsm_x4(ah[mt], st + offA[mt] + ((((ks * 2 + lkA) ^ qA[mt])) << 4));
            #pragma unroll
            for (int P = 0; P < 2; P++)
                ldsm_x4(bh[P], bst + offB[P] + ((((ks * 2 + b_kh) ^ qB[P])) << 4));
            #pragma unroll
            for (int mt = 0; mt < 2; mt++)
                #pragma unroll
                for (int nt = 0; nt < 4; nt++)
                    mma_fp16(acc[mt][nt], ah[mt], &bh[nt >> 1][(nt & 1) * 2]);
        }
    };

    const int nch = Kk / TBK;

    #pragma unroll
    for (int p = 0; p < NSTAGE - 1; p++) {
        if (p < nch) issue_copy(p, p * TBK);
        cp_commit();
    }

    for (int ch = 0; ch < nch; ch++) {
        cp_wait<NSTAGE - 2>();
        __syncthreads();
        int nxt = ch + NSTAGE - 1;
        if (nxt < nch) issue_copy(nxt % NSTAGE, nxt * TBK);
        cp_commit();
        compute(ch % NSTAGE);
    }

    // epilogue
    #pragma unroll
    for (int mt = 0; mt < 2; mt++) {
        int r0 = m0 + wm * 32 + mt * 16 + g;
        #pragma unroll
        for (int nt = 0; nt < 4; nt++) {
            int col = n0 + wn * 32 + nt * 8 + t4 * 2;
            if (EPI == 0) {
                uint32_t* chp = (uint32_t*)Ch;
                size_t base = (size_t)blockIdx.z * sC;
                chp[(base + (size_t)r0 * ldc + col) >> 1] =
                    pack_h2(acc[mt][nt][0], acc[mt][nt][1]);
                chp[(base + (size_t)(r0 + 8) * ldc + col) >> 1] =
                    pack_h2(acc[mt][nt][2], acc[mt][nt][3]);
            } else {
                float b0 = __ldg(bias + col), b1 = __ldg(bias + col + 1);
                float* p0 = Cf + (size_t)r0 * ldc + col;
                float* p1 = Cf + (size_t)(r0 + 8) * ldc + col;
                *(float2*)p0 = make_float2(acc[mt][nt][0] + b0, acc[mt][nt][1] + b1);
                *(float2*)p1 = make_float2(acc[mt][nt][2] + b0, acc[mt][nt][3] + b1);
            }
        }
    }
}

// ---------------------------------------------------------------------------
extern "C" void kernel_launch(void* const* d_in, const int* in_sizes, int n_in,
                              void* d_out, int out_size) {
    const float* x       = (const float*)d_in[0];  // [B,N,C]
    const float* centers = (const float*)d_in[1];  // [C,K]
    const float* tran_ms = (const float*)d_in[2];  // [K,N,N]
    const float* proj_w  = (const float*)d_in[3];  // [C,C]
    const float* proj_b  = (const float*)d_in[4];  // [C]
    float* out = (float*)d_out;                    // [B,N,C]

    __half *tm16, *xt16, *y16, *w16;
    cudaGetSymbolAddress((void**)&tm16, g_tm16);
    cudaGetSymbolAddress((void**)&xt16, g_xT16);
    cudaGetSymbolAddress((void**)&y16, g_y16);
    cudaGetSymbolAddress((void**)&w16, g_W16);

    cudaFuncSetAttribute(gemm_fp16<0>, cudaFuncAttributeMaxDynamicSharedMemorySize,
                         GSMEM_BYTES);
    cudaFuncSetAttribute(gemm_fp16<1>, cudaFuncAttributeMaxDynamicSharedMemorySize,
                         GSMEM_BYTES);

    // launch #1: conversions + pooling partials (fused)
    convert_kernel<<<dim3(N_/32, C_/32, B_ + 2), dim3(32, 8)>>>(x, proj_w);

    // launch #2: routing weights
    attn_kernel<<<B_, C_>>>(centers);

    // launch #3: tm = attn @ tran_ms -> fp16
    tm_kernel<<<(NN_/2) / 128, 128>>>(tran_ms);

    // launch #4 (ncu capture slot): y[b] = tm[b] @ x[b] -> fp16
    gemm_fp16<0><<<dim3(N_/TBM, C_/TBN, B_), 256, GSMEM_BYTES>>>(
        tm16, xt16, nullptr, y16, nullptr,
        /*K=*/N_, /*lda=*/N_, /*ldb=*/N_, /*ldc=*/C_,
        (size_t)NN_, (size_t)C_ * N_, (size_t)N_ * C_);

    // launch #5: out = y @ W^T + b -> f32
    gemm_fp16<1><<<dim3((B_*N_)/TBM, C_/TBN, 1), 256, GSMEM_BYTES>>>(
        y16, w16, out, nullptr, proj_b,
        /*K=*/C_, /*lda=*/C_, /*ldb=*/C_, /*ldc=*/C_,
        0, 0, 0);
}

// round 13
// speedup vs baseline: 1.4705x; 1.0516x over previous
#include <cuda_runtime.h>
#include <cuda_fp16.h>
#include <cstdint>

// Problem shapes (fixed by the dataset)
#define B_ 16
#define N_ 512
#define C_ 384
#define K_ 64
#define NN_ (N_*N_)

// Scratch (no allocs allowed -> __device__ globals)
__device__ float g_qpart[B_][8][C_];
__device__ float g_attn[B_*K_];
__device__ __half g_tm16[(size_t)B_*NN_];    // tm   [B][512][512] fp16
__device__ __half g_xT16[(size_t)B_*C_*N_];  // xT   [B][C][N]    fp16
__device__ __half g_y16[(size_t)B_*N_*C_];   // y    [B*N][C]     fp16
__device__ __half g_W16[C_*C_];              // W    [C][C]       fp16

__device__ __forceinline__ uint32_t smem_u32(const void* p) {
    uint32_t a;
    asm("{ .reg .u64 t; cvta.to.shared.u64 t, %1; cvt.u32.u64 %0, t; }"
        : "=r"(a) : "l"(p));
    return a;
}
__device__ __forceinline__ void cp_async16(uint32_t dst, const void* src) {
    asm volatile("cp.async.cg.shared.global [%0], [%1], 16;"
                 :: "r"(dst), "l"(src) : "memory");
}
__device__ __forceinline__ void cp_commit() {
    asm volatile("cp.async.commit_group;" ::: "memory");
}
template <int NMax>
__device__ __forceinline__ void cp_wait() {
    asm volatile("cp.async.wait_group %0;" :: "n"(NMax) : "memory");
}
__device__ __forceinline__ void ldsm_x4(uint32_t* r, uint32_t addr) {
    asm volatile("ldmatrix.sync.aligned.m8n8.x4.shared.b16 {%0,%1,%2,%3}, [%4];"
        : "=r"(r[0]), "=r"(r[1]), "=r"(r[2]), "=r"(r[3]) : "r"(addr));
}
__device__ __forceinline__ void ldsm_x4_t(uint32_t* r, uint32_t addr) {
    asm volatile("ldmatrix.sync.aligned.m8n8.x4.trans.shared.b16 {%0,%1,%2,%3}, [%4];"
        : "=r"(r[0]), "=r"(r[1]), "=r"(r[2]), "=r"(r[3]) : "r"(addr));
}
__device__ __forceinline__ void mma_fp16(float* c, const uint32_t* a, const uint32_t* b) {
    asm volatile(
        "mma.sync.aligned.m16n8k16.row.col.f32.f16.f16.f32 "
        "{%0,%1,%2,%3}, {%4,%5,%6,%7}, {%8,%9}, {%0,%1,%2,%3};"
        : "+f"(c[0]), "+f"(c[1]), "+f"(c[2]), "+f"(c[3])
        : "r"(a[0]), "r"(a[1]), "r"(a[2]), "r"(a[3]), "r"(b[0]), "r"(b[1]));
}
__device__ __forceinline__ uint32_t pack_h2(float a, float b) {
    __half2 h = __floats2half2_rn(a, b);
    return *(uint32_t*)&h;
}

// ---------------------------------------------------------------------------
// Kernel 1 (launch #1): fused pool partials + transpose_x(+fp16) + W fp16.
// grid (16, 12, 18): z<16 transpose slices; z==16 W; z==17 pooling.
// ---------------------------------------------------------------------------
__global__ void convert_kernel(const float* __restrict__ x,
                               const float* __restrict__ W) {
    if (blockIdx.z == 16) {
        int tid = (blockIdx.y * 16 + blockIdx.x) * 256 +
                  threadIdx.y * 32 + threadIdx.x;
        for (int i = tid; i < C_ * C_; i += 192 * 256)
            g_W16[i] = __float2half_rn(W[i]);
        return;
    }
    if (blockIdx.z == 17) {
        int blk = blockIdx.y * 16 + blockIdx.x;       // 0..191
        if (blk >= B_ * 8) return;
        int b = blk >> 3, seg = blk & 7;
        int t = threadIdx.y * 32 + threadIdx.x;       // 0..255
        const float* xb = x + (size_t)b * N_ * C_ + (size_t)seg * 64 * C_;
        for (int c = t; c < C_; c += 256) {
            float s = 0.f;
            #pragma unroll 8
            for (int n = 0; n < 64; n++) s += xb[(size_t)n * C_ + c];
            g_qpart[b][seg][c] = s;
        }
        return;
    }
    __shared__ float t[32][33];
    int b = blockIdx.z;
    int n0 = blockIdx.x * 32, c0 = blockIdx.y * 32;
    int tx = threadIdx.x, ty = threadIdx.y;   // 32 x 8
    #pragma unroll
    for (int i = 0; i < 4; i++)
        t[ty + i * 8][tx] = x[(size_t)b * N_ * C_ + (size_t)(n0 + ty + i * 8) * C_ + c0 + tx];
    __syncthreads();
    #pragma unroll
    for (int i = 0; i < 4; i++) {
        float v = t[tx][ty + i * 8];
        size_t o = (size_t)b * C_ * N_ + (size_t)(c0 + ty + i * 8) * N_ + n0 + tx;
        g_xT16[o] = __float2half_rn(v);
    }
}

// ---------------------------------------------------------------------------
// Kernel 2 (launch #2): finish pool + normalize + logits + softmax -> g_attn
// ---------------------------------------------------------------------------
__global__ void attn_kernel(const float* __restrict__ centers) {
    int b = blockIdx.x;
    int tid = threadIdx.x;
    __shared__ float s_q[C_];
    __shared__ float s_red[C_];
    __shared__ float s_logit[K_];
    __shared__ float s_mx, s_den;

    float sum = 0.f;
    #pragma unroll
    for (int seg = 0; seg < 8; seg++) sum += g_qpart[b][seg][tid];
    s_q[tid] = sum * (1.0f / N_);
    __syncthreads();

    float v = s_q[tid];
    s_red[tid] = v * v;
    __syncthreads();
    if (tid < 128) s_red[tid] += s_red[tid + 128] + s_red[tid + 256];
    __syncthreads();
    for (int s = 64; s > 0; s >>= 1) {
        if (tid < s) s_red[tid] += s_red[tid + s];
        __syncthreads();
    }
    float qnorm = sqrtf(s_red[0]);

    if (tid < K_) {
        float dot = 0.f, cs = 0.f;
        #pragma unroll 4
        for (int c = 0; c < C_; c++) {
            float w = centers[(size_t)c * K_ + tid];
            dot += s_q[c] * w;
            cs  += w * w;
        }
        float denom = fmaxf(qnorm, 1e-12f) * fmaxf(sqrtf(cs), 1e-12f);
        s_logit[tid] = dot / denom;
    }
    __syncthreads();

    if (tid == 0) {
        float mx = -1e30f;
        for (int k = 0; k < K_; k++) mx = fmaxf(mx, s_logit[k]);
        float den = 0.f;
        for (int k = 0; k < K_; k++) den += expf(s_logit[k] - mx);
        s_mx = mx; s_den = den;
    }
    __syncthreads();
    if (tid < K_) g_attn[b * K_ + tid] = expf(s_logit[tid] - s_mx) / s_den;
}

// ---------------------------------------------------------------------------
// Kernel 3 (launch #3): tm via TENSOR CORES.
// tm[b,nm] = sum_k attn[b,k] * tran[k,nm]:  GEMM M=16(b), K=64, N=nm.
// Per CTA: 128-nm chunk. tran fp32 -> fp16 smem tile [64k][128nm] (swizzled),
// attn fp16 smem [16b][64k] (swizzled). A via ldmatrix, B via ldmatrix.trans,
// 8 warps x 16nm each, D written as half2.
// ---------------------------------------------------------------------------
__global__ __launch_bounds__(256)
void tm_tc_kernel(const float* __restrict__ tran) {
    __shared__ __align__(16) __half s_tr[64 * 128];   // 16KB, swizzled
    __shared__ __align__(16) __half s_at[16 * 64];    // 2KB,  swizzled

    const int tid = threadIdx.x;
    const int warp = tid >> 5, lane = tid & 31;
    const int g = lane >> 2, t4 = lane & 3;
    const int nm0 = blockIdx.x * 128;

    // ---- load attn [16 b][64 k] fp32 -> fp16 smem (swizzled 16B chunks) ----
    {
        int b = tid >> 4, kq = tid & 15;              // kq: float4 index (4 k)
        float4 av = *(const float4*)(g_attn + b * 64 + kq * 4);
        uint2 hv;
        hv.x = pack_h2(av.x, av.y);
        hv.y = pack_h2(av.z, av.w);
        int chunk = kq >> 1;                          // 16B chunk (8 k)
        int base = b * 64 + ((chunk ^ (b & 7)) << 3) + (kq & 1) * 4;  // half idx
        *(uint2*)(s_at + base) = hv;
    }

    // ---- load tran [64 k][128 nm] fp32 -> fp16 smem (swizzled) ----
    #pragma unroll
    for (int i = 0; i < 8; i++) {
        int f = tid + 256 * i;                        // 0..2047
        int k = f >> 5, c4 = f & 31;                  // c4: float4 along nm
        float4 v = *(const float4*)(tran + (size_t)k * NN_ + nm0 + c4 * 4);
        uint2 hv;
        hv.x = pack_h2(v.x, v.y);
        hv.y = pack_h2(v.z, v.w);
        int chunk = c4 >> 1;
        int base = k * 128 + ((chunk ^ (k & 7)) << 3) + (c4 & 1) * 4;
        *(uint2*)(s_tr + base) = hv;
    }
    __syncthreads();

    // ---- A fragments (attn), 4 k-chunks of 16 ----
    const uint32_t at_base = smem_u32(s_at);
    uint32_t a[4][4];
    {
        int sub = lane >> 3;
        int br = ((sub & 1) << 3) + (lane & 7);       // b row
        #pragma unroll
        for (int kc = 0; kc < 4; kc++) {
            int ch16 = kc * 2 + (sub >> 1);
            uint32_t ad = at_base + br * 128 + ((ch16 ^ (br & 7)) << 4);
            ldsm_x4(a[kc], ad);
        }
    }

    // ---- B fragments (tran, trans) + MMA. Warp handles nm [w*16, w*16+16) ----
    const uint32_t tr_base = smem_u32(s_tr);
    float acc[2][4] = {{0.f,0.f,0.f,0.f},{0.f,0.f,0.f,0.f}};
    {
        int sub = lane >> 3;
        int krow_off = ((sub & 1) << 3) + (lane & 7); // k within 16-chunk
        int nch8 = warp * 2 + (sub >> 1);             // nm 8-chunk index
        #pragma unroll
        for (int kc = 0; kc < 4; kc++) {
            int k = kc * 16 + krow_off;
            uint32_t bd = tr_base + k * 256 + ((nch8 ^ (k & 7)) << 4);
            uint32_t bt[4];
            ldsm_x4_t(bt, bd);
            mma_fp16(acc[0], a[kc], &bt[0]);          // nm lo8
            mma_fp16(acc[1], a[kc], &bt[2]);          // nm hi8
        }
    }

    // ---- store D: rows = b, cols = nm ----
    uint32_t* out = (uint32_t*)g_tm16;
    #pragma unroll
    for (int n8 = 0; n8 < 2; n8++) {
        int col = nm0 + warp * 16 + n8 * 8 + 2 * t4;
        out[((size_t)g * NN_ + col) >> 1]       = pack_h2(acc[n8][0], acc[n8][1]);
        out[((size_t)(g + 8) * NN_ + col) >> 1] = pack_h2(acc[n8][2], acc[n8][3]);
    }
}

// ---------------------------------------------------------------------------
// fp16 tensor-core GEMM (mma.sync m16n8k16 f32.f16.f16.f32), single term.
// CTA 128x64x32, 8 warps (4m x 2n), warp tile 32x32. (unchanged from R12)
// ---------------------------------------------------------------------------
#define TBM 128
#define TBN 64
#define TBK 32
#define A_BYTES (TBM*TBK*2)            // 8192
#define B_BYTES (TBN*TBK*2)            // 4096
#define STAGE_BYTES (A_BYTES + B_BYTES)        // 12288
#define NSTAGE 3
#define GSMEM_BYTES (NSTAGE*STAGE_BYTES)       // 36864

template <int EPI>
__global__ __launch_bounds__(256, 3)
void gemm_fp16(const __half* __restrict__ A, const __half* __restrict__ Bm,
               float* __restrict__ Cf, __half* __restrict__ Ch,
               const float* __restrict__ bias,
               int Kk, int lda, int ldb, int ldc,
               size_t sA, size_t sB, size_t sC) {
    extern __shared__ char sm[];

    const int tid = threadIdx.x;
    const int warp = tid >> 5, lane = tid & 31;
    const int wm = warp >> 1, wn = warp & 1;      // 4 x 2 warp grid
    const int g = lane >> 2, t4 = lane & 3;

    const int m0 = blockIdx.x * TBM, n0 = blockIdx.y * TBN;
    const __half* Ab = A  + (size_t)blockIdx.z * sA;
    const __half* Bb = Bm + (size_t)blockIdx.z * sB;

    const uint32_t smb = smem_u32(sm);

    auto issue_copy = [&](int s, int k0) {
        uint32_t st = smb + (uint32_t)s * STAGE_BYTES;
        #pragma unroll
        for (int i = 0; i < 2; i++) {
            int id = tid + 256 * i;
            int r = id >> 2, c = id & 3;
            uint32_t d = st + (uint32_t)(r * 64 + ((c ^ ((r >> 1) & 3)) << 4));
            cp_async16(d, Ab + (size_t)(m0 + r) * lda + k0 + c * 8);
        }
        {
            uint32_t bst = st + A_BYTES;
            int r = tid >> 2, c = tid & 3;
            uint32_t d = bst + (uint32_t)(r * 64 + ((c ^ ((r >> 1) & 3)) << 4));
            cp_async16(d, Bb + (size_t)(n0 + r) * ldb + k0 + c * 8);
        }
    };

    float acc[2][4][4];
    #pragma unroll
    for (int mt = 0; mt < 2; mt++)
        #pragma unroll
        for (int nt = 0; nt < 4; nt++)
            #pragma unroll
            for (int q = 0; q < 4; q++) acc[mt][nt][q] = 0.f;

    const int lrA = lane & 15, lkA = (lane >> 4) & 1;
    int offA[2], qA[2];
    #pragma unroll
    for (int mt = 0; mt < 2; mt++) {
        int r = wm * 32 + mt * 16 + lrA;
        offA[mt] = r * 64;
        qA[mt] = (r >> 1) & 3;
    }
    const int b_ntloc = (lane >> 4) & 1, b_kh = (lane >> 3) & 1;
    int offB[2], qB[2];
    #pragma unroll
    for (int P = 0; P < 2; P++) {
        int r = wn * 32 + P * 16 + b_ntloc * 8 + (lane & 7);
        offB[P] = r * 64;
        qB[P] = (r >> 1) & 3;
    }

    auto compute = [&](int s) {
        uint32_t st = smb + (uint32_t)s * STAGE_BYTES;
        uint32_t bst = st + A_BYTES;
        #pragma unroll
        for (int ks = 0; ks < 2; ks++) {
            uint32_t ah[2][4], bh[2][4];
            #pragma unroll
            for (int mt = 0; mt < 2; mt++)
                ldsm_x4(ah[mt], st + offA[mt] + ((((ks * 2 + lkA) ^ qA[mt])) << 4));
            #pragma unroll
            for (int P = 0; P < 2; P++)
                ldsm_x4(bh[P], bst + offB[P] + ((((ks * 2 + b_kh) ^ qB[P])) << 4));
            #pragma unroll
            for (int mt = 0; mt < 2; mt++)
                #pragma unroll
                for (int nt = 0; nt < 4; nt++)
                    mma_fp16(acc[mt][nt], ah[mt], &bh[nt >> 1][(nt & 1) * 2]);
        }
    };

    const int nch = Kk / TBK;

    #pragma unroll
    for (int p = 0; p < NSTAGE - 1; p++) {
        if (p < nch) issue_copy(p, p * TBK);
        cp_commit();
    }

    for (int ch = 0; ch < nch; ch++) {
        cp_wait<NSTAGE - 2>();
        __syncthreads();
        int nxt = ch + NSTAGE - 1;
        if (nxt < nch) issue_copy(nxt % NSTAGE, nxt * TBK);
        cp_commit();
        compute(ch % NSTAGE);
    }

    // epilogue
    #pragma unroll
    for (int mt = 0; mt < 2; mt++) {
        int r0 = m0 + wm * 32 + mt * 16 + g;
        #pragma unroll
        for (int nt = 0; nt < 4; nt++) {
            int col = n0 + wn * 32 + nt * 8 + t4 * 2;
            if (EPI == 0) {
                uint32_t* chp = (uint32_t*)Ch;
                size_t base = (size_t)blockIdx.z * sC;
                chp[(base + (size_t)r0 * ldc + col) >> 1] =
                    pack_h2(acc[mt][nt][0], acc[mt][nt][1]);
                chp[(base + (size_t)(r0 + 8) * ldc + col) >> 1] =
                    pack_h2(acc[mt][nt][2], acc[mt][nt][3]);
            } else {
                float b0 = __ldg(bias + col), b1 = __ldg(bias + col + 1);
                float* p0 = Cf + (size_t)r0 * ldc + col;
                float* p1 = Cf + (size_t)(r0 + 8) * ldc + col;
                *(float2*)p0 = make_float2(acc[mt][nt][0] + b0, acc[mt][nt][1] + b1);
                *(float2*)p1 = make_float2(acc[mt][nt][2] + b0, acc[mt][nt][3] + b1);
            }
        }
    }
}

// ---------------------------------------------------------------------------
extern "C" void kernel_launch(void* const* d_in, const int* in_sizes, int n_in,
                              void* d_out, int out_size) {
    const float* x       = (const float*)d_in[0];  // [B,N,C]
    const float* centers = (const float*)d_in[1];  // [C,K]
    const float* tran_ms = (const float*)d_in[2];  // [K,N,N]
    const float* proj_w  = (const float*)d_in[3];  // [C,C]
    const float* proj_b  = (const float*)d_in[4];  // [C]
    float* out = (float*)d_out;                    // [B,N,C]

    __half *tm16, *xt16, *y16, *w16;
    cudaGetSymbolAddress((void**)&tm16, g_tm16);
    cudaGetSymbolAddress((void**)&xt16, g_xT16);
    cudaGetSymbolAddress((void**)&y16, g_y16);
    cudaGetSymbolAddress((void**)&w16, g_W16);

    cudaFuncSetAttribute(gemm_fp16<0>, cudaFuncAttributeMaxDynamicSharedMemorySize,
                         GSMEM_BYTES);
    cudaFuncSetAttribute(gemm_fp16<1>, cudaFuncAttributeMaxDynamicSharedMemorySize,
                         GSMEM_BYTES);

    // launch #1: conversions + pooling partials (fused)
    convert_kernel<<<dim3(N_/32, C_/32, B_ + 2), dim3(32, 8)>>>(x, proj_w);

    // launch #2: routing weights
    attn_kernel<<<B_, C_>>>(centers);

    // launch #3: tm = attn @ tran_ms via tensor cores -> fp16
    tm_tc_kernel<<<NN_ / 128, 256>>>(tran_ms);

    // launch #4 (ncu capture slot): y[b] = tm[b] @ x[b] -> fp16
    gemm_fp16<0><<<dim3(N_/TBM, C_/TBN, B_), 256, GSMEM_BYTES>>>(
        tm16, xt16, nullptr, y16, nullptr,
        /*K=*/N_, /*lda=*/N_, /*ldb=*/N_, /*ldc=*/C_,
        (size_t)NN_, (size_t)C_ * N_, (size_t)N_ * C_);

    // launch #5: out = y @ W^T + b -> f32
    gemm_fp16<1><<<dim3((B_*N_)/TBM, C_/TBN, 1), 256, GSMEM_BYTES>>>(
        y16, w16, out, nullptr, proj_b,
        /*K=*/C_, /*lda=*/C_, /*ldb=*/C_, /*ldc=*/C_,
        0, 0, 0);
}